// round 1
// baseline (speedup 1.0000x reference)
#include <cuda_runtime.h>

// HandGraphConvNet: fused 2-layer GCN + BN(eval) + relu + residual.
// x: (S,B,42) fp32, 21 joints x 2 channels. Math (BN folded, reassociated):
//   Y  = A @ X                      (per sample, 21x2)
//   H  = relu(Y @ W1' + beta1')    W1' = W1 * alpha1 (col), beta1' = (b1-m1)*alpha1 + be1
//   S2 = H @ W2'                   W2' = W2 * alpha2 (col)
//   out = A @ S2 + beta2' + x      beta2' = (b2-m2)*alpha2 + be2
// One thread per (sample, joint); H never materialized (fused channel loop).

#define NJ 21
#define HIDDEN 64
#define HDIM 42
#define SPB 32                 // samples per block
#define NTHREADS (NJ * 32)     // 672: warp <-> joint, lane <-> local sample
#define XS_STRIDE 43           // pad: gcd(43,32)=1 -> conflict-free lane-strided reads
#define BN_EPS 1e-5f

__device__ __forceinline__ unsigned long long pk2(float lo, float hi) {
    unsigned long long r;
    asm("mov.b64 %0, {%1, %2};" : "=l"(r) : "f"(lo), "f"(hi));
    return r;
}
__device__ __forceinline__ void upk2(unsigned long long v, float& lo, float& hi) {
    asm("mov.b64 {%0, %1}, %2;" : "=f"(lo), "=f"(hi) : "l"(v));
}
// Blackwell packed fp32 pipe: 2 FMAs per instruction
__device__ __forceinline__ unsigned long long ffma2(unsigned long long a,
                                                    unsigned long long b,
                                                    unsigned long long c) {
    unsigned long long d;
    asm("fma.rn.f32x2 %0, %1, %2, %3;" : "=l"(d) : "l"(a), "l"(b), "l"(c));
    return d;
}

__global__ __launch_bounds__(NTHREADS)
void hand_gcn_kernel(const float* __restrict__ x,  const float* __restrict__ adj,
                     const float* __restrict__ W1, const float* __restrict__ b1,
                     const float* __restrict__ W2, const float* __restrict__ b2,
                     const float* __restrict__ g1, const float* __restrict__ be1,
                     const float* __restrict__ m1, const float* __restrict__ v1,
                     const float* __restrict__ g2, const float* __restrict__ be2,
                     const float* __restrict__ m2, const float* __restrict__ v2,
                     float* __restrict__ out, int nsamples)
{
    __shared__ float  xs [SPB * XS_STRIDE];   // staged X, later reused for staged output
    __shared__ float  s2s[SPB * XS_STRIDE];   // per-sample S2 (21x2)
    __shared__ float  adjs[NJ * NJ];
    __shared__ float4 cka[32];                // (W1'[0][2c],W1'[0][2c+1],W1'[1][2c],W1'[1][2c+1])
    __shared__ float4 ckb[32];                // (W2'[2c][0],W2'[2c+1][0],W2'[2c][1],W2'[2c+1][1])
    __shared__ float2 ckc[32];                // (beta1'[2c], beta1'[2c+1])
    __shared__ float2 beta2s;

    const int tid = threadIdx.x;
    const int j   = tid >> 5;    // joint (warp id)
    const int sl  = tid & 31;    // local sample (lane)
    const long long base  = (long long)blockIdx.x * (SPB * HDIM);
    const int total = nsamples * HDIM;

    // ---- stage X (coalesced), adjacency, folded constants ----
    #pragma unroll
    for (int i = tid; i < SPB * HDIM; i += NTHREADS) {
        long long g = base + i;
        float v = (g < total) ? x[g] : 0.f;
        xs[(i / HDIM) * XS_STRIDE + (i % HDIM)] = v;
    }
    for (int i = tid; i < NJ * NJ; i += NTHREADS) adjs[i] = adj[i];

    if (tid < 32) {
        int c0 = 2 * tid, c1 = c0 + 1;
        float al0 = g1[c0] * rsqrtf(v1[c0] + BN_EPS);
        float al1 = g1[c1] * rsqrtf(v1[c1] + BN_EPS);
        cka[tid] = make_float4(W1[c0] * al0, W1[c1] * al1,
                               W1[HIDDEN + c0] * al0, W1[HIDDEN + c1] * al1);
        ckc[tid] = make_float2((b1[c0] - m1[c0]) * al0 + be1[c0],
                               (b1[c1] - m1[c1]) * al1 + be1[c1]);
        float a20 = g2[0] * rsqrtf(v2[0] + BN_EPS);
        float a21 = g2[1] * rsqrtf(v2[1] + BN_EPS);
        ckb[tid] = make_float4(W2[c0 * 2] * a20, W2[c1 * 2] * a20,
                               W2[c0 * 2 + 1] * a21, W2[c1 * 2 + 1] * a21);
        if (tid == 0)
            beta2s = make_float2((b2[0] - m2[0]) * a20 + be2[0],
                                 (b2[1] - m2[1]) * a21 + be2[1]);
    }
    __syncthreads();

    // ---- Y = (A @ X)[j] for this thread's (sample, joint) ----
    float* xrow = &xs[sl * XS_STRIDE];
    const float* arow = &adjs[j * NJ];
    float y0 = 0.f, y1 = 0.f;
    #pragma unroll
    for (int jj = 0; jj < NJ; ++jj) {
        float a = arow[jj];                    // uniform within warp -> broadcast
        y0 = fmaf(a, xrow[2 * jj],     y0);
        y1 = fmaf(a, xrow[2 * jj + 1], y1);
    }

    // ---- fused layer1 (transform+BN+relu) -> layer2 channel contraction ----
    unsigned long long y0d = pk2(y0, y0), y1d = pk2(y1, y1);
    unsigned long long acc0 = 0ULL, acc1 = 0ULL;   // (0.f, 0.f)
    #pragma unroll
    for (int cp = 0; cp < 32; ++cp) {
        float4 wa = cka[cp];
        float2 bp = ckc[cp];
        float4 wb = ckb[cp];
        unsigned long long h =
            ffma2(y0d, pk2(wa.x, wa.y),
            ffma2(y1d, pk2(wa.z, wa.w), pk2(bp.x, bp.y)));
        float hl, hh; upk2(h, hl, hh);
        hl = fmaxf(hl, 0.f); hh = fmaxf(hh, 0.f);
        h = pk2(hl, hh);
        acc0 = ffma2(h, pk2(wb.x, wb.y), acc0);
        acc1 = ffma2(h, pk2(wb.z, wb.w), acc1);
    }
    float a0l, a0h, a1l, a1h;
    upk2(acc0, a0l, a0h);
    upk2(acc1, a1l, a1h);
    float* s2row = &s2s[sl * XS_STRIDE];
    s2row[2 * j]     = a0l + a0h;
    s2row[2 * j + 1] = a1l + a1h;
    __syncthreads();

    // ---- out[j] = (A @ S2)[j] + beta2' + x[j] ----
    float o0 = beta2s.x, o1 = beta2s.y;
    #pragma unroll
    for (int jj = 0; jj < NJ; ++jj) {
        float a = arow[jj];
        o0 = fmaf(a, s2row[2 * jj],     o0);
        o1 = fmaf(a, s2row[2 * jj + 1], o1);
    }
    o0 += xrow[2 * j];
    o1 += xrow[2 * j + 1];
    // overwrite own X slot (sole reader == sole writer in this phase)
    xrow[2 * j]     = o0;
    xrow[2 * j + 1] = o1;
    __syncthreads();

    // ---- coalesced store ----
    #pragma unroll
    for (int i = tid; i < SPB * HDIM; i += NTHREADS) {
        long long g = base + i;
        if (g < total) out[g] = xs[(i / HDIM) * XS_STRIDE + (i % HDIM)];
    }
}

extern "C" void kernel_launch(void* const* d_in, const int* in_sizes, int n_in,
                              void* d_out, int out_size) {
    int nsamples = in_sizes[0] / HDIM;
    int grid = (nsamples + SPB - 1) / SPB;
    hand_gcn_kernel<<<grid, NTHREADS>>>(
        (const float*)d_in[0],  (const float*)d_in[1],  (const float*)d_in[2],
        (const float*)d_in[3],  (const float*)d_in[4],  (const float*)d_in[5],
        (const float*)d_in[6],  (const float*)d_in[7],  (const float*)d_in[8],
        (const float*)d_in[9],  (const float*)d_in[10], (const float*)d_in[11],
        (const float*)d_in[12], (const float*)d_in[13],
        (float*)d_out, nsamples);
}